// round 1
// baseline (speedup 1.0000x reference)
#include <cuda_runtime.h>

// VectorQuantizer: argmax_k ( W[k] . z ), then emit W[argmax], index, commit loss.
// W: 131072 x 1024 f32 (512 MiB) -> HBM-bound streaming problem.
// Output layout assumed: [quantized_st (1024 f32), index (as f32), loss (f32)].

#define VQ_DIM   1024
#define VQ_ROWS  131072
#define ARG_BLOCKS  2048
#define ARG_THREADS 256

// Global scratch for the packed (key, ~row) argmax result.
__device__ unsigned long long g_vq_best;

__global__ void vq_init_kernel() {
    g_vq_best = 0ULL;  // below any valid key for finite dots
}

// Monotonic float -> uint key: preserves ordering for all finite floats.
__device__ __forceinline__ unsigned float_key(float f) {
    unsigned u = __float_as_uint(f);
    return (u & 0x80000000u) ? ~u : (u | 0x80000000u);
}

__global__ __launch_bounds__(ARG_THREADS, 2)
void vq_argmax_kernel(const float* __restrict__ z, const float* __restrict__ W) {
    __shared__ float zs[VQ_DIM];
    __shared__ unsigned long long blk_best;

    const int tid  = threadIdx.x;
    const int lane = tid & 31;

    if (tid == 0) blk_best = 0ULL;
    // Stage z into shared (4 KB), vectorized.
    const float4* z4 = (const float4*)z;
    float4* zs4 = (float4*)zs;
    for (int i = tid; i < VQ_DIM / 4; i += ARG_THREADS)
        zs4[i] = z4[i];
    __syncthreads();

    const int gwarp  = (blockIdx.x * ARG_THREADS + tid) >> 5;
    const int nwarps = (ARG_BLOCKS * ARG_THREADS) >> 5;   // 16384 warps -> 8 rows/warp

    unsigned long long best = 0ULL;

    for (int row = gwarp; row < VQ_ROWS; row += nwarps) {
        const float4* wr = (const float4*)(W + (size_t)row * VQ_DIM);
        // Each lane covers 8 float4 chunks of the 1024-elem row (lane + 32*it).
        // 4 accumulators + full unroll -> front-batched independent LDG.128s (MLP).
        float a0 = 0.f, a1 = 0.f, a2 = 0.f, a3 = 0.f;
        #pragma unroll
        for (int it = 0; it < 8; it += 4) {
            float4 w0 = wr[lane + (it + 0) * 32];
            float4 w1 = wr[lane + (it + 1) * 32];
            float4 w2 = wr[lane + (it + 2) * 32];
            float4 w3 = wr[lane + (it + 3) * 32];
            float4 p0 = zs4[lane + (it + 0) * 32];
            float4 p1 = zs4[lane + (it + 1) * 32];
            float4 p2 = zs4[lane + (it + 2) * 32];
            float4 p3 = zs4[lane + (it + 3) * 32];
            a0 += w0.x * p0.x + w0.y * p0.y + w0.z * p0.z + w0.w * p0.w;
            a1 += w1.x * p1.x + w1.y * p1.y + w1.z * p1.z + w1.w * p1.w;
            a2 += w2.x * p2.x + w2.y * p2.y + w2.z * p2.z + w2.w * p2.w;
            a3 += w3.x * p3.x + w3.y * p3.y + w3.z * p3.z + w3.w * p3.w;
        }
        float dot = (a0 + a1) + (a2 + a3);
        // Warp tree-reduce.
        #pragma unroll
        for (int off = 16; off; off >>= 1)
            dot += __shfl_xor_sync(0xffffffffu, dot, off);

        if (lane == 0) {
            // Pack (key, inverted row): ties resolve to the SMALLEST row index,
            // matching jnp.argmax first-occurrence semantics.
            unsigned long long p =
                ((unsigned long long)float_key(dot) << 32) |
                (unsigned long long)(0xFFFFFFFFu - (unsigned)row);
            if (p > best) best = p;
        }
    }

    if (lane == 0) atomicMax(&blk_best, best);
    __syncthreads();
    if (tid == 0) atomicMax(&g_vq_best, blk_best);
}

__global__ void vq_finalize_kernel(const float* __restrict__ z,
                                   const float* __restrict__ W,
                                   float* __restrict__ out, int out_size) {
    __shared__ float red[256];
    const int tid = threadIdx.x;

    const unsigned row = 0xFFFFFFFFu - (unsigned)(g_vq_best & 0xFFFFFFFFull);
    const float* q = W + (size_t)row * VQ_DIM;

    float s = 0.f;
    for (int i = tid; i < VQ_DIM; i += 256) {
        float qi = q[i];
        float d  = z[i] - qi;
        s += d * d;
        if (i < out_size) out[i] = qi;   // quantized_st == quantized numerically
    }
    red[tid] = s;
    __syncthreads();
    #pragma unroll
    for (int o = 128; o; o >>= 1) {
        if (tid < o) red[tid] += red[tid + o];
        __syncthreads();
    }
    if (tid == 0) {
        if (out_size >= VQ_DIM + 1) out[VQ_DIM] = (float)row;           // index
        if (out_size >= VQ_DIM + 2) out[VQ_DIM + 1] = 0.25f * red[0] / (float)VQ_DIM; // loss
    }
}

extern "C" void kernel_launch(void* const* d_in, const int* in_sizes, int n_in,
                              void* d_out, int out_size) {
    // metadata order: z (1024), W (131072*1024) — verify by size just in case.
    const float* z = (const float*)d_in[0];
    const float* W = (const float*)d_in[1];
    if (n_in >= 2 && in_sizes[0] != VQ_DIM && in_sizes[1] == VQ_DIM) {
        z = (const float*)d_in[1];
        W = (const float*)d_in[0];
    }
    float* out = (float*)d_out;

    vq_init_kernel<<<1, 1>>>();
    vq_argmax_kernel<<<ARG_BLOCKS, ARG_THREADS>>>(z, W);
    vq_finalize_kernel<<<1, 256>>>(z, W, out, out_size);
}